// round 11
// baseline (speedup 1.0000x reference)
#include <cuda_runtime.h>
#include <cuda_fp16.h>
#include <math.h>

#define NTHREADS 256
#define HID 64
#define GRID 148   // 1 CTA per SM, persistent

typedef unsigned long long u64;
typedef unsigned int u32;

// ---------------- SMEM layout (float offsets) ----------------
#define OFF_SW1 0
#define OFF_SB1 448
#define OFF_SW2 512
#define OFF_SB2 4608
#define OFF_SW3 4672
#define OFF_SB3 4736
#define OFF_AW1 4740
#define OFF_AB1 5188
#define OFF_AW2 5252
#define OFF_AB2 9348
#define OFF_AW3 9412
#define OFF_AB3 9476
#define OFF_FW1 9480
#define OFF_FB1 9864
#define OFF_FW2 9928
#define OFF_FB2 14024
#define OFF_FW3 14088
#define OFF_FB3 14152
#define OFF_RW1 14156
#define OFF_RB1 14476
#define OFF_RW2 14540
#define OFF_RB2 18636
#define OFF_RW3 18700
#define OFF_RB3 18892
#define OFF_IMEAN 18896
#define OFF_ISTD  18904
#define OFF_TMEAN 18912
#define OFF_TSTD  18916
#define OFF_ACT   18920                    // u64 per (neuron, thread): 4 rows as fp16x4
#define ACT_U64   (NTHREADS * HID)         // 16384 u64 = 128 KB
#define SMEM_BYTES (OFF_ACT * 4 + ACT_U64 * 8)   // 206752 B

struct KParams {
    const float* in[30];
    float* out;
    int B;
};

__device__ __constant__ int kCnt[28] = {
    5, 5, 3, 3,
    448, 64, 4096, 64, 64, 1,
    448, 64, 4096, 64, 64, 1,
    384, 64, 4096, 64, 64, 1,
    320, 64, 4096, 64, 192, 3
};
__device__ __constant__ int kOff[28] = {
    OFF_IMEAN, OFF_ISTD, OFF_TMEAN, OFF_TSTD,
    OFF_SW1, OFF_SB1, OFF_SW2, OFF_SB2, OFF_SW3, OFF_SB3,
    OFF_AW1, OFF_AB1, OFF_AW2, OFF_AB2, OFF_AW3, OFF_AB3,
    OFF_FW1, OFF_FB1, OFF_FW2, OFF_FB2, OFF_FW3, OFF_FB3,
    OFF_RW1, OFF_RB1, OFF_RW2, OFF_RB2, OFF_RW3, OFF_RB3
};

// ---------------- packed helpers ----------------
__device__ __forceinline__ u64 dup2(float a) {
    u64 r; asm("mov.b64 %0, {%1, %1};" : "=l"(r) : "f"(a)); return r;
}
__device__ __forceinline__ u64 ffma2(u64 a, u64 b, u64 c) {
    u64 d; asm("fma.rn.f32x2 %0, %1, %2, %3;" : "=l"(d) : "l"(a), "l"(b), "l"(c)); return d;
}
__device__ __forceinline__ float2 unpk2(u64 a) {
    float2 f; asm("mov.b64 {%0, %1}, %2;" : "=f"(f.x), "=f"(f.y) : "l"(a)); return f;
}
// pack 4 f32 -> 4 fp16 in one u64 (first operand of cvt.f16x2 is HIGH half)
__device__ __forceinline__ u64 pack_h4(float a, float b, float c, float d) {
    u32 lo, hi;
    asm("cvt.rn.f16x2.f32 %0, %1, %2;" : "=r"(lo) : "f"(b), "f"(a));
    asm("cvt.rn.f16x2.f32 %0, %1, %2;" : "=r"(hi) : "f"(d), "f"(c));
    u64 r; asm("mov.b64 %0, {%1, %2};" : "=l"(r) : "r"(lo), "r"(hi));
    return r;
}
__device__ __forceinline__ float4 unpack_h4(u64 v) {
    u32 lo, hi;
    asm("mov.b64 {%0, %1}, %2;" : "=r"(lo), "=r"(hi) : "l"(v));
    __half2 h0 = *reinterpret_cast<__half2*>(&lo);
    __half2 h1 = *reinterpret_cast<__half2*>(&hi);
    float2 f0 = __half22float2(h0);
    float2 f1 = __half22float2(h1);
    return make_float4(f0.x, f0.y, f1.x, f1.y);
}

// HW tanh: 1 MUFU op (hidden layers)
__device__ __forceinline__ float tanh_hw(float x) {
    float r; asm("tanh.approx.f32 %0, %1;" : "=f"(r) : "f"(x)); return r;
}
// accurate tanh for the two FINAL activations
__device__ __forceinline__ float tanh_exact(float x) {
    float ax = fabsf(x);
    float e  = __expf(2.0f * ax);
    float t  = 1.0f - __fdividef(2.0f, e + 1.0f);
    return (x < 0.0f) ? -t : t;
}
__device__ __forceinline__ float softplusf(float x) {
    float t = __expf(-fabsf(x));
    return fmaxf(x, 0.0f) + __logf(1.0f + t);
}

// FOUR rows through one MLP: DIN -> 64 (tanh) -> 64 (tanh) -> DOUT.
// Phase 1: layer-1 in FOUR 16-output slices (acc = 64 regs co-live);
// tanh(h1) -> SMEM as fp16x4.
// Phase 2: layer-2 in two 32-col chunks (acc = 128 regs, x[] dead by then).
// Every weight LDS feeds 8 FFMA2 (4 rows).
template <int DIN, int DOUT>
__device__ __forceinline__ void run_mlp4(
    const float* __restrict__ x,      // [4*DIN], row-major
    const float* __restrict__ sm,
    u64* __restrict__ act,            // offset by tid; stride NTHREADS
    int oW1, int ob1, int oW2, int ob2, int oW3, int ob3,
    float* __restrict__ outm)         // [4*DOUT]
{
    // ---- phase 1: layer 1, four 16-output slices ----
#pragma unroll
    for (int s = 0; s < 4; s++) {
        u64 acc[4][8];
        {
            const ulonglong2* b1 = (const ulonglong2*)(sm + ob1 + s * 16);
#pragma unroll
            for (int j = 0; j < 4; j++) {
                ulonglong2 b = b1[j];
#pragma unroll
                for (int r = 0; r < 4; r++) { acc[r][2*j] = b.x; acc[r][2*j+1] = b.y; }
            }
        }
#pragma unroll
        for (int i = 0; i < DIN; i++) {
            const ulonglong2* w = (const ulonglong2*)(sm + oW1 + i * HID + s * 16);
            u64 xd[4];
#pragma unroll
            for (int r = 0; r < 4; r++) xd[r] = dup2(x[r * DIN + i]);
#pragma unroll
            for (int j = 0; j < 4; j++) {
                ulonglong2 wv = w[j];
#pragma unroll
                for (int r = 0; r < 4; r++) {
                    acc[r][2*j]   = ffma2(xd[r], wv.x, acc[r][2*j]);
                    acc[r][2*j+1] = ffma2(xd[r], wv.y, acc[r][2*j+1]);
                }
            }
        }
        // tanh -> fp16x4 -> smem
#pragma unroll
        for (int j = 0; j < 8; j++) {
            float2 v0 = unpk2(acc[0][j]);
            float2 v1 = unpk2(acc[1][j]);
            float2 v2 = unpk2(acc[2][j]);
            float2 v3 = unpk2(acc[3][j]);
            act[(s*16 + 2*j)   * NTHREADS] = pack_h4(tanh_hw(v0.x), tanh_hw(v1.x), tanh_hw(v2.x), tanh_hw(v3.x));
            act[(s*16 + 2*j+1) * NTHREADS] = pack_h4(tanh_hw(v0.y), tanh_hw(v1.y), tanh_hw(v2.y), tanh_hw(v3.y));
        }
    }

    // ---- phase 2: layer 2 in two 32-col chunks + streaming layer 3 ----
    float o[4][DOUT];
#pragma unroll
    for (int oo = 0; oo < DOUT; oo++) {
        float b = sm[ob3 + oo];
#pragma unroll
        for (int r = 0; r < 4; r++) o[r][oo] = b;
    }

#pragma unroll
    for (int chunk = 0; chunk < 2; chunk++) {
        u64 acc[4][16];
        {
            const ulonglong2* b2 = (const ulonglong2*)(sm + ob2 + chunk * 32);
#pragma unroll
            for (int j = 0; j < 8; j++) {
                ulonglong2 b = b2[j];
#pragma unroll
                for (int r = 0; r < 4; r++) { acc[r][2*j] = b.x; acc[r][2*j+1] = b.y; }
            }
        }
#pragma unroll 4
        for (int k = 0; k < HID; k++) {
            float4 h = unpack_h4(act[k * NTHREADS]);
            u64 d0 = dup2(h.x), d1 = dup2(h.y), d2 = dup2(h.z), d3 = dup2(h.w);
            const ulonglong2* w = (const ulonglong2*)(sm + oW2 + k * HID + chunk * 32);
#pragma unroll
            for (int j = 0; j < 8; j++) {
                ulonglong2 wv = w[j];
                acc[0][2*j]   = ffma2(d0, wv.x, acc[0][2*j]);
                acc[0][2*j+1] = ffma2(d0, wv.y, acc[0][2*j+1]);
                acc[1][2*j]   = ffma2(d1, wv.x, acc[1][2*j]);
                acc[1][2*j+1] = ffma2(d1, wv.y, acc[1][2*j+1]);
                acc[2][2*j]   = ffma2(d2, wv.x, acc[2][2*j]);
                acc[2][2*j+1] = ffma2(d2, wv.y, acc[2][2*j+1]);
                acc[3][2*j]   = ffma2(d3, wv.x, acc[3][2*j]);
                acc[3][2*j+1] = ffma2(d3, wv.y, acc[3][2*j+1]);
            }
        }
        // tanh + layer-3 partial for cols [chunk*32, chunk*32+32)
#pragma unroll
        for (int j = 0; j < 16; j++) {
            int base = chunk * 32 + 2*j;
#pragma unroll
            for (int r = 0; r < 4; r++) {
                float2 v = unpk2(acc[r][j]);
                float t0 = tanh_hw(v.x), t1 = tanh_hw(v.y);
#pragma unroll
                for (int oo = 0; oo < DOUT; oo++) {
                    float w0 = sm[oW3 + base * DOUT + oo];
                    float w1 = sm[oW3 + (base + 1) * DOUT + oo];
                    o[r][oo] = fmaf(t0, w0, fmaf(t1, w1, o[r][oo]));
                }
            }
        }
    }
#pragma unroll
    for (int r = 0; r < 4; r++)
#pragma unroll
        for (int oo = 0; oo < DOUT; oo++) outm[r * DOUT + oo] = o[r][oo];
}

extern __shared__ float sm[];

__global__ void __launch_bounds__(NTHREADS, 1)
fused_mlp_kernel(KParams p)
{
    const int tid = threadIdx.x;

    // Stage all weights + norm params into SMEM once per CTA.
    for (int a = 0; a < 28; a++) {
        const float* src = p.in[a + 2];
        const int n = kCnt[a];
        const int o = kOff[a];
        for (int k = tid; k < n; k += NTHREADS) sm[o + k] = src[k];
    }
    __syncthreads();

    u64* act = (u64*)(sm + OFF_ACT) + tid;

    const float* xd0 = p.in[0];
    const float* utr = p.in[1];
    const int Btot = p.B;
    const int nquads = (Btot + 3) >> 2;
    const int stride = gridDim.x * NTHREADS;

    const float im0 = sm[OFF_IMEAN+0], im1 = sm[OFF_IMEAN+1], im2 = sm[OFF_IMEAN+2];
    const float im3 = sm[OFF_IMEAN+3], im4 = sm[OFF_IMEAN+4];
    const float is0 = sm[OFF_ISTD+0],  is1 = sm[OFF_ISTD+1],  is2 = sm[OFF_ISTD+2];
    const float is3 = sm[OFF_ISTD+3],  is4 = sm[OFF_ISTD+4];

    for (int q = blockIdx.x * NTHREADS + tid; q < nquads; q += stride) {
        const int r0 = 4 * q;
        float f[4][5];   // vx, vy, w, vel, delta per row
        if (r0 + 3 < Btot) {
            const float4* x4 = (const float4*)(xd0 + (size_t)r0 * 3);
            float4 A = x4[0], Bv = x4[1], C = x4[2];
            const float4* u4 = (const float4*)(utr + (size_t)r0 * 2);
            float4 U = u4[0], V = u4[1];
            f[0][0]=A.x;  f[0][1]=A.y;  f[0][2]=A.z;  f[0][3]=U.x; f[0][4]=U.y;
            f[1][0]=A.w;  f[1][1]=Bv.x; f[1][2]=Bv.y; f[1][3]=U.z; f[1][4]=U.w;
            f[2][0]=Bv.z; f[2][1]=Bv.w; f[2][2]=C.x;  f[2][3]=V.x; f[2][4]=V.y;
            f[3][0]=C.y;  f[3][1]=C.z;  f[3][2]=C.w;  f[3][3]=V.z; f[3][4]=V.w;
        } else {
#pragma unroll
            for (int r = 0; r < 4; r++) {
                int rr = min(r0 + r, Btot - 1);
                f[r][0] = xd0[rr*3+0]; f[r][1] = xd0[rr*3+1]; f[r][2] = xd0[rr*3+2];
                f[r][3] = utr[rr*2+0]; f[r][4] = utr[rr*2+1];
            }
        }
        float vm[4], sg[4];
#pragma unroll
        for (int r = 0; r < 4; r++) {
            f[r][0] = __fdividef(f[r][0] - im0, is0);
            f[r][1] = __fdividef(f[r][1] - im1, is1);
            f[r][2] = __fdividef(f[r][2] - im2, is2);
            f[r][3] = __fdividef(f[r][3] - im3, is3);
            f[r][4] = __fdividef(f[r][4] - im4, is4);
            vm[r] = sqrtf(fmaf(f[r][0], f[r][0], fmaf(f[r][1], f[r][1], 1e-8f)));
            sg[r] = (f[r][0] > 0.0f) ? 1.0f : ((f[r][0] < 0.0f) ? -1.0f : 0.0f);
        }

        // steer MLP: [delta, vel, vx, vy, w, mag, sign]
        float si[28], so[4];
#pragma unroll
        for (int r = 0; r < 4; r++) {
            si[r*7+0]=f[r][4]; si[r*7+1]=f[r][3]; si[r*7+2]=f[r][0];
            si[r*7+3]=f[r][1]; si[r*7+4]=f[r][2]; si[r*7+5]=vm[r]; si[r*7+6]=sg[r];
        }
        run_mlp4<7,1>(si, sm, act, OFF_SW1, OFF_SB1, OFF_SW2, OFF_SB2, OFF_SW3, OFF_SB3, so);

        // acc MLP: [vel, delta, vx, mag, sign, vy, w]
        float ai[28], ao[4];
#pragma unroll
        for (int r = 0; r < 4; r++) {
            ai[r*7+0]=f[r][3]; ai[r*7+1]=f[r][4]; ai[r*7+2]=f[r][0];
            ai[r*7+3]=vm[r];   ai[r*7+4]=sg[r];   ai[r*7+5]=f[r][1]; ai[r*7+6]=f[r][2];
        }
        run_mlp4<7,1>(ai, sm, act, OFF_AW1, OFF_AB1, OFF_AW2, OFF_AB2, OFF_AW3, OFF_AB3, ao);

        float ue0[4], ue1[4];
#pragma unroll
        for (int r = 0; r < 4; r++) {
            ue0[r] = f[r][3] + 0.5f * tanh_exact(ao[r]);
            ue1[r] = f[r][4] + 0.5f * tanh_exact(so[r]);
        }

        // friction MLP: [vx, vy, w, ue0, ue1, DT]
        float fi[24], fo[4];
#pragma unroll
        for (int r = 0; r < 4; r++) {
            fi[r*6+0]=f[r][0]; fi[r*6+1]=f[r][1]; fi[r*6+2]=f[r][2];
            fi[r*6+3]=ue0[r];  fi[r*6+4]=ue1[r];  fi[r*6+5]=0.02f;
        }
        run_mlp4<6,1>(fi, sm, act, OFF_FW1, OFF_FB1, OFF_FW2, OFF_FB2, OFF_FW3, OFF_FB3, fo);

        // residual MLP: [vx, vy, w, ue0, ue1]
        float ri[20], ro[12];
#pragma unroll
        for (int r = 0; r < 4; r++) {
            ri[r*5+0]=f[r][0]; ri[r*5+1]=f[r][1]; ri[r*5+2]=f[r][2];
            ri[r*5+3]=ue0[r];  ri[r*5+4]=ue1[r];
        }
        run_mlp4<5,3>(ri, sm, act, OFF_RW1, OFF_RB1, OFF_RW2, OFF_RB2, OFF_RW3, OFF_RB3, ro);

        const float ts0 = sm[OFF_TSTD+0], ts1 = sm[OFF_TSTD+1], ts2 = sm[OFF_TSTD+2];
        const float tm0 = sm[OFF_TMEAN+0], tm1 = sm[OFF_TMEAN+1], tm2 = sm[OFF_TMEAN+2];

        // outputs: [ut_eff_raw (B,2)] [friction_k (B,1)] [residual (B,3)]
#pragma unroll
        for (int r = 0; r < 4; r++) {
            int row = r0 + r;
            if (row < Btot) {
                p.out[row*2+0] = fmaf(ue0[r], is3, im3);
                p.out[row*2+1] = fmaf(ue1[r], is4, im4);
                p.out[2*Btot + row] = 1.0f + softplusf(fo[r]);
                p.out[3*Btot + row*3 + 0] = fmaf(ro[r*3+0], ts0, tm0);
                p.out[3*Btot + row*3 + 1] = fmaf(ro[r*3+1], ts1, tm1);
                p.out[3*Btot + row*3 + 2] = fmaf(ro[r*3+2], ts2, tm2);
            }
        }
    }
}

extern "C" void kernel_launch(void* const* d_in, const int* in_sizes, int n_in,
                              void* d_out, int out_size)
{
    KParams p;
    for (int i = 0; i < 30; i++) p.in[i] = (const float*)d_in[i];
    p.out = (float*)d_out;
    p.B = in_sizes[0] / 3;

    cudaFuncSetAttribute(fused_mlp_kernel,
                         cudaFuncAttributeMaxDynamicSharedMemorySize, SMEM_BYTES);
    fused_mlp_kernel<<<GRID, NTHREADS, SMEM_BYTES>>>(p);
}

// round 12
// speedup vs baseline: 2.0486x; 2.0486x over previous
#include <cuda_runtime.h>
#include <math.h>

typedef unsigned long long u64;
typedef unsigned int u32;

#define NTH 384
#define NW 12
#define GRID 148

// ---- smem word offsets ----
// per-MLP weight block: W1p(tf32)[8][64]=512 | b1 f32[64] | W2(tf32)[64][64]=4096 |
//                       b2 f32[64] | W3 f32[64][DOUT] | b3 f32[DOUT]
#define MLP_S 0          // steer  (DOUT 1, size 4801)
#define MLP_A 4801       // acc
#define MLP_F 9602       // friction
#define MLP_R 14403      // residual (DOUT 3, size 4931)
#define AS_OFF 19336     // per-warp A-stage: [32][9] tf32 words
#define FS_OFF 22792     // per-warp features: [32][9] f32
#define HS_OFF 26248     // per-warp hidden:  [32][68] tf32 words (padded stride)
#define SMEM_WORDS 52360
#define SMEM_BYTES (SMEM_WORDS * 4)   // 209440 B

struct KParams {
    const float* in[30];
    float* out;
    int B;
};

// ---------------- helpers ----------------
__device__ __forceinline__ u32 f2tf(float x) {
    u32 r; asm("cvt.rna.tf32.f32 %0, %1;" : "=r"(r) : "f"(x)); return r;
}
__device__ __forceinline__ float tanh_hw(float x) {
    float r; asm("tanh.approx.f32 %0, %1;" : "=f"(r) : "f"(x)); return r;
}
__device__ __forceinline__ float tanh_exact(float x) {
    float ax = fabsf(x);
    float e  = __expf(2.0f * ax);
    float t  = 1.0f - __fdividef(2.0f, e + 1.0f);
    return (x < 0.0f) ? -t : t;
}
__device__ __forceinline__ float softplusf(float x) {
    float t = __expf(-fabsf(x));
    return fmaxf(x, 0.0f) + __logf(1.0f + t);
}
// m16n8k8 tf32 MMA, D = A*B + D
__device__ __forceinline__ void mma8(float& c0, float& c1, float& c2, float& c3,
                                     u32 a0, u32 a1, u32 a2, u32 a3, u32 b0, u32 b1) {
    asm("mma.sync.aligned.m16n8k8.row.col.f32.tf32.tf32.f32 "
        "{%0,%1,%2,%3}, {%4,%5,%6,%7}, {%8,%9}, {%0,%1,%2,%3};"
        : "+f"(c0), "+f"(c1), "+f"(c2), "+f"(c3)
        : "r"(a0), "r"(a1), "r"(a2), "r"(a3), "r"(b0), "r"(b1));
}

// One MLP (8->64 tanh -> 64 tanh -> DOUT) for 32 rows, warp-cooperative.
// As: staged inputs [32][9] tf32. Hs: hidden scratch [32][68] tf32.
// y[t][j][o] = output for row (t*16 + g + j*8), identical across the 4 lanes of a quad.
template <int DOUT>
__device__ __forceinline__ void run_mlp_mma(
    const u32* __restrict__ wb, const u32* __restrict__ As, u32* __restrict__ Hs,
    int g, int ti, float (&y)[2][2][DOUT])
{
    const float* B1 = (const float*)(wb + 512);
    const u32*   W2 = wb + 576;
    const float* B2 = (const float*)(wb + 4672);
    const float* W3 = (const float*)(wb + 4736);
    const float* B3 = W3 + 64 * DOUT;

    // ---- layer 1: [32x8] @ [8x64], one k-step per row-tile ----
#pragma unroll
    for (int t = 0; t < 2; t++) {
        u32 a0 = As[(t*16 + g)     * 9 + ti];
        u32 a1 = As[(t*16 + g + 8) * 9 + ti];
        u32 a2 = As[(t*16 + g)     * 9 + ti + 4];
        u32 a3 = As[(t*16 + g + 8) * 9 + ti + 4];
#pragma unroll
        for (int n = 0; n < 8; n++) {
            float c0 = B1[n*8 + 2*ti], c1 = B1[n*8 + 2*ti + 1];
            float c2 = c0, c3 = c1;
            u32 b0 = wb[ti*64       + n*8 + g];
            u32 b1 = wb[(ti+4)*64   + n*8 + g];
            mma8(c0, c1, c2, c3, a0, a1, a2, a3, b0, b1);
            u32 h0 = f2tf(tanh_hw(c0)), h1 = f2tf(tanh_hw(c1));
            u32 h2 = f2tf(tanh_hw(c2)), h3 = f2tf(tanh_hw(c3));
            int r0 = (t*16 + g)     * 68 + n*8 + 2*ti;
            int r1 = (t*16 + g + 8) * 68 + n*8 + 2*ti;
            *(u64*)(Hs + r0) = (u64)h0 | ((u64)h1 << 32);
            *(u64*)(Hs + r1) = (u64)h2 | ((u64)h3 << 32);
        }
    }
    __syncwarp();

    // ---- layer 2: [32x64] @ [64x64] + streaming layer 3 ----
#pragma unroll
    for (int t = 0; t < 2; t++) {
        u32 A0[8], A1[8], A2[8], A3[8];
#pragma unroll
        for (int k = 0; k < 8; k++) {
            int b0i = (t*16 + g)     * 68 + k*8;
            int b1i = (t*16 + g + 8) * 68 + k*8;
            A0[k] = Hs[b0i + ti];  A2[k] = Hs[b0i + ti + 4];
            A1[k] = Hs[b1i + ti];  A3[k] = Hs[b1i + ti + 4];
        }
        float p0[DOUT], p1[DOUT];
#pragma unroll
        for (int o = 0; o < DOUT; o++) { p0[o] = 0.0f; p1[o] = 0.0f; }
#pragma unroll
        for (int n = 0; n < 8; n++) {
            float c0 = B2[n*8 + 2*ti], c1 = B2[n*8 + 2*ti + 1];
            float c2 = c0, c3 = c1;
#pragma unroll
            for (int k = 0; k < 8; k++) {
                u32 b0 = W2[(k*8 + ti)     * 64 + n*8 + g];
                u32 b1 = W2[(k*8 + ti + 4) * 64 + n*8 + g];
                mma8(c0, c1, c2, c3, A0[k], A1[k], A2[k], A3[k], b0, b1);
            }
            float t0 = tanh_hw(c0), t1 = tanh_hw(c1);
            float t2 = tanh_hw(c2), t3 = tanh_hw(c3);
#pragma unroll
            for (int o = 0; o < DOUT; o++) {
                float w0 = W3[(n*8 + 2*ti)     * DOUT + o];
                float w1 = W3[(n*8 + 2*ti + 1) * DOUT + o];
                p0[o] += t0 * w0 + t1 * w1;
                p1[o] += t2 * w0 + t3 * w1;
            }
        }
#pragma unroll
        for (int o = 0; o < DOUT; o++) {
            p0[o] += __shfl_xor_sync(0xffffffffu, p0[o], 1);
            p0[o] += __shfl_xor_sync(0xffffffffu, p0[o], 2);
            p1[o] += __shfl_xor_sync(0xffffffffu, p1[o], 1);
            p1[o] += __shfl_xor_sync(0xffffffffu, p1[o], 2);
            y[t][0][o] = p0[o] + B3[o];
            y[t][1][o] = p1[o] + B3[o];
        }
    }
    __syncwarp();
}

extern __shared__ u32 smu[];

__global__ void __launch_bounds__(NTH, 1)
fused_mlp_kernel(KParams p)
{
    float* smf = (float*)smu;
    const int tid = threadIdx.x;

    // ---- stage weights: W1 zero-padded to 8 rows, W1/W2 pre-cvt to tf32 ----
    const int DINs[4]  = {7, 7, 6, 5};
    const int DOUTs[4] = {1, 1, 1, 3};
    const int WOFF[4]  = {MLP_S, MLP_A, MLP_F, MLP_R};
    for (int m = 0; m < 4; m++) {
        const float* W1 = p.in[6 + m*6 + 0];
        const float* B1 = p.in[6 + m*6 + 1];
        const float* W2 = p.in[6 + m*6 + 2];
        const float* B2 = p.in[6 + m*6 + 3];
        const float* W3 = p.in[6 + m*6 + 4];
        const float* B3 = p.in[6 + m*6 + 5];
        int base = WOFF[m], din = DINs[m], dout = DOUTs[m];
        for (int i = tid; i < 512; i += NTH) {
            int r = i >> 6;
            smu[base + i] = (r < din) ? f2tf(W1[r*64 + (i & 63)]) : 0u;
        }
        for (int i = tid; i < 64; i += NTH)   smf[base + 512 + i]  = B1[i];
        for (int i = tid; i < 4096; i += NTH) smu[base + 576 + i]  = f2tf(W2[i]);
        for (int i = tid; i < 64; i += NTH)   smf[base + 4672 + i] = B2[i];
        for (int i = tid; i < 64*dout; i += NTH) smf[base + 4736 + i] = W3[i];
        for (int i = tid; i < dout; i += NTH) smf[base + 4736 + 64*dout + i] = B3[i];
    }
    __syncthreads();

    const float im0 = p.in[2][0], im1 = p.in[2][1], im2 = p.in[2][2], im3 = p.in[2][3], im4 = p.in[2][4];
    const float is0 = p.in[3][0], is1 = p.in[3][1], is2 = p.in[3][2], is3 = p.in[3][3], is4 = p.in[3][4];
    const float tm0 = p.in[4][0], tm1 = p.in[4][1], tm2 = p.in[4][2];
    const float ts0 = p.in[5][0], ts1 = p.in[5][1], ts2 = p.in[5][2];

    const int w = tid >> 5, lane = tid & 31, g = lane >> 2, ti = lane & 3;
    u32*   As = smu + AS_OFF + w * 288;
    float* Fs = smf + FS_OFF + w * 288;
    u32*   Hs = smu + HS_OFF + w * 2176;

    const float* xd0 = p.in[0];
    const float* utr = p.in[1];
    const int B = p.B;
    const int ntasks = (B + 31) >> 5;

    for (int task = blockIdx.x * NW + w; task < ntasks; task += GRID * NW) {
        __syncwarp();
        const int row = task * 32 + lane;
        const int rc  = min(row, B - 1);

        float vx    = __fdividef(xd0[rc*3 + 0] - im0, is0);
        float vy    = __fdividef(xd0[rc*3 + 1] - im1, is1);
        float wz    = __fdividef(xd0[rc*3 + 2] - im2, is2);
        float vel   = __fdividef(utr[rc*2 + 0] - im3, is3);
        float delta = __fdividef(utr[rc*2 + 1] - im4, is4);
        float vmag  = sqrtf(fmaf(vx, vx, fmaf(vy, vy, 1e-8f)));
        float vsg   = (vx > 0.0f) ? 1.0f : ((vx < 0.0f) ? -1.0f : 0.0f);

        Fs[lane*9 + 0] = vx; Fs[lane*9 + 1] = vy; Fs[lane*9 + 2] = wz;
        Fs[lane*9 + 3] = vel; Fs[lane*9 + 4] = delta;

        // ---- steer MLP: [delta, vel, vx, vy, w, mag, sign, 0] ----
        As[lane*9 + 0] = f2tf(delta); As[lane*9 + 1] = f2tf(vel);
        As[lane*9 + 2] = f2tf(vx);    As[lane*9 + 3] = f2tf(vy);
        As[lane*9 + 4] = f2tf(wz);    As[lane*9 + 5] = f2tf(vmag);
        As[lane*9 + 6] = f2tf(vsg);   As[lane*9 + 7] = 0u;
        __syncwarp();
        float ys_[2][2][1];
        run_mlp_mma<1>(smu + MLP_S, As, Hs, g, ti, ys_);

        // ---- acc MLP: [vel, delta, vx, mag, sign, vy, w, 0] ----
        As[lane*9 + 0] = f2tf(vel);  As[lane*9 + 1] = f2tf(delta);
        As[lane*9 + 2] = f2tf(vx);   As[lane*9 + 3] = f2tf(vmag);
        As[lane*9 + 4] = f2tf(vsg);  As[lane*9 + 5] = f2tf(vy);
        As[lane*9 + 6] = f2tf(wz);   As[lane*9 + 7] = 0u;
        __syncwarp();
        float ya_[2][2][1];
        run_mlp_mma<1>(smu + MLP_A, As, Hs, g, ti, ya_);

        // ---- ue per lane's 4 rows; ti==0 lane publishes to Fs ----
#pragma unroll
        for (int t = 0; t < 2; t++)
#pragma unroll
            for (int j = 0; j < 2; j++) {
                int lr = t*16 + g + j*8;
                float velr   = Fs[lr*9 + 3];
                float deltar = Fs[lr*9 + 4];
                float u0 = velr   + 0.5f * tanh_exact(ya_[t][j][0]);
                float u1 = deltar + 0.5f * tanh_exact(ys_[t][j][0]);
                if (ti == 0) { Fs[lr*9 + 5] = u0; Fs[lr*9 + 6] = u1; }
            }
        __syncwarp();

        // ---- ut_eff_raw store (row-owner, coalesced float2) ----
        {
            float u0 = fmaf(Fs[lane*9 + 5], is3, im3);
            float u1 = fmaf(Fs[lane*9 + 6], is4, im4);
            if (row < B) ((float2*)p.out)[row] = make_float2(u0, u1);
        }

        // ---- friction MLP: [vx, vy, w, ue0, ue1, DT, 0, 0] ----
        As[lane*9 + 0] = f2tf(Fs[lane*9 + 0]); As[lane*9 + 1] = f2tf(Fs[lane*9 + 1]);
        As[lane*9 + 2] = f2tf(Fs[lane*9 + 2]); As[lane*9 + 3] = f2tf(Fs[lane*9 + 5]);
        As[lane*9 + 4] = f2tf(Fs[lane*9 + 6]); As[lane*9 + 5] = f2tf(0.02f);
        As[lane*9 + 6] = 0u;                   As[lane*9 + 7] = 0u;
        __syncwarp();
        float yf_[2][2][1];
        run_mlp_mma<1>(smu + MLP_F, As, Hs, g, ti, yf_);
        if (ti == 0) {
#pragma unroll
            for (int t = 0; t < 2; t++)
#pragma unroll
                for (int j = 0; j < 2; j++) {
                    int rr = task*32 + t*16 + g + j*8;
                    if (rr < B) p.out[2*B + rr] = 1.0f + softplusf(yf_[t][j][0]);
                }
        }

        // ---- residual MLP: [vx, vy, w, ue0, ue1, 0, 0, 0] ----
        As[lane*9 + 0] = f2tf(Fs[lane*9 + 0]); As[lane*9 + 1] = f2tf(Fs[lane*9 + 1]);
        As[lane*9 + 2] = f2tf(Fs[lane*9 + 2]); As[lane*9 + 3] = f2tf(Fs[lane*9 + 5]);
        As[lane*9 + 4] = f2tf(Fs[lane*9 + 6]); As[lane*9 + 5] = 0u;
        As[lane*9 + 6] = 0u;                   As[lane*9 + 7] = 0u;
        __syncwarp();
        float yr_[2][2][3];
        run_mlp_mma<3>(smu + MLP_R, As, Hs, g, ti, yr_);
        if (ti == 0) {
#pragma unroll
            for (int t = 0; t < 2; t++)
#pragma unroll
                for (int j = 0; j < 2; j++) {
                    int rr = task*32 + t*16 + g + j*8;
                    if (rr < B) {
                        p.out[3*B + rr*3 + 0] = fmaf(yr_[t][j][0], ts0, tm0);
                        p.out[3*B + rr*3 + 1] = fmaf(yr_[t][j][1], ts1, tm1);
                        p.out[3*B + rr*3 + 2] = fmaf(yr_[t][j][2], ts2, tm2);
                    }
                }
        }
    }
}

extern "C" void kernel_launch(void* const* d_in, const int* in_sizes, int n_in,
                              void* d_out, int out_size)
{
    KParams p;
    for (int i = 0; i < 30; i++) p.in[i] = (const float*)d_in[i];
    p.out = (float*)d_out;
    p.B = in_sizes[0] / 3;

    cudaFuncSetAttribute(fused_mlp_kernel,
                         cudaFuncAttributeMaxDynamicSharedMemorySize, SMEM_BYTES);
    fused_mlp_kernel<<<GRID, NTH, SMEM_BYTES>>>(p);
}